// round 2
// baseline (speedup 1.0000x reference)
#include <cuda_runtime.h>

#define BB 512
#define SS 512
#define DD 512
#define LN_EPS 1e-5f
#define INV_SCALE 0.125f   // 1/sqrt(64)

// ---------------- scratch (__device__ globals; no allocation allowed) ----------------
__device__ float d_LNs[BB*DD];    // LN(sentiment)
__device__ float d_Wqk[DD*DD];    // Wq @ Wk^T
__device__ float d_qk[BB*DD];     // LNs @ Wqk
__device__ float d_gqk[BB*DD];    // g_kv * (qk + wkbq) / 8
__device__ float d_c1[BB];
__device__ float d_c2[BB];
__device__ float d_yv[BB*DD];     // sum_s attn*rstd*x
__device__ float d_tv[BB];        // sum_s attn*rstd*m
__device__ float d_Wvo[DD*DD];    // Wv @ Wo
__device__ float d_bvo[DD];       // bv @ Wo + bo
__device__ float d_LNa[BB*DD];    // attn-weighted LN vector
__device__ float d_ctxo[BB*DD];   // context after Wo
__device__ float d_G[BB*DD];      // gate pre-activation
__device__ float d_wkbq[DD];      // Wk @ bq
__device__ float d_wqbk[DD];      // Wq @ bk
__device__ float d_bqbk;          // bq . bk

// ---------------- block reductions (128 threads) ----------------
__device__ __forceinline__ void bred2_128(float& a, float& b) {
#pragma unroll
    for (int o = 16; o; o >>= 1) {
        a += __shfl_xor_sync(0xffffffffu, a, o);
        b += __shfl_xor_sync(0xffffffffu, b, o);
    }
    __shared__ float sa[4], sb[4];
    int w = threadIdx.x >> 5;
    if ((threadIdx.x & 31) == 0) { sa[w] = a; sb[w] = b; }
    __syncthreads();
    a = sa[0] + sa[1] + sa[2] + sa[3];
    b = sb[0] + sb[1] + sb[2] + sb[3];
}

__device__ __forceinline__ void bred3_128(float& a, float& b, float& c) {
#pragma unroll
    for (int o = 16; o; o >>= 1) {
        a += __shfl_xor_sync(0xffffffffu, a, o);
        b += __shfl_xor_sync(0xffffffffu, b, o);
        c += __shfl_xor_sync(0xffffffffu, c, o);
    }
    __shared__ float sa[4], sb[4], sc[4];
    int w = threadIdx.x >> 5;
    if ((threadIdx.x & 31) == 0) { sa[w] = a; sb[w] = b; sc[w] = c; }
    __syncthreads();
    a = sa[0] + sa[1] + sa[2] + sa[3];
    b = sb[0] + sb[1] + sb[2] + sb[3];
    c = sc[0] + sc[1] + sc[2] + sc[3];
}

// ---------------- LN of sentiment: one block per batch row ----------------
__global__ void k_ln_sent(const float* __restrict__ sent,
                          const float* __restrict__ g, const float* __restrict__ be) {
    int b = blockIdx.x, t = threadIdx.x;
    const float4* row = (const float4*)(sent + (size_t)b * DD);
    float4 x = row[t];
    float s = x.x + x.y + x.z + x.w;
    float ss = fmaf(x.x, x.x, fmaf(x.y, x.y, fmaf(x.z, x.z, x.w * x.w)));
    bred2_128(s, ss);
    float m = s * (1.0f / DD);
    float var = ss * (1.0f / DD) - m * m;
    float r = rsqrtf(var + LN_EPS);
    float4 gg = ((const float4*)g)[t];
    float4 bb = ((const float4*)be)[t];
    float4 o;
    o.x = (x.x - m) * r * gg.x + bb.x;
    o.y = (x.y - m) * r * gg.y + bb.y;
    o.z = (x.z - m) * r * gg.z + bb.z;
    o.w = (x.w - m) * r * gg.w + bb.w;
    ((float4*)(d_LNs + (size_t)b * DD))[t] = o;
}

// ---------------- bias matvecs: wkbq[e]=Wk[e,:].bq  wqbk[e]=Wq[e,:].bk  bqbk ----------------
__global__ void k_bias_prep(const float* __restrict__ Wk, const float* __restrict__ bq,
                            const float* __restrict__ Wq, const float* __restrict__ bk) {
    int e = blockIdx.x, t = threadIdx.x;
    float a = 0.f, b2 = 0.f, c = 0.f;
    for (int d = t; d < DD; d += 128) {
        a  = fmaf(Wk[(size_t)e * DD + d], bq[d], a);
        b2 = fmaf(Wq[(size_t)e * DD + d], bk[d], b2);
        c  = fmaf(bq[d], bk[d], c);
    }
    bred3_128(a, b2, c);
    if (t == 0) {
        d_wkbq[e] = a;
        d_wqbk[e] = b2;
        if (e == 0) d_bqbk = c;
    }
}

// ---------------- per-batch score constants: gqk, c1, c2 ----------------
__global__ void k_prep(const float* __restrict__ g_kv, const float* __restrict__ beta_kv) {
    int b = blockIdx.x, t = threadIdx.x;
    float4 qv = ((const float4*)(d_qk + (size_t)b * DD))[t];
    float4 wb = ((const float4*)d_wkbq)[t];
    qv.x = (qv.x + wb.x) * INV_SCALE;
    qv.y = (qv.y + wb.y) * INV_SCALE;
    qv.z = (qv.z + wb.z) * INV_SCALE;
    qv.w = (qv.w + wb.w) * INV_SCALE;
    float4 gv = ((const float4*)g_kv)[t];
    float4 bv = ((const float4*)beta_kv)[t];
    float4 gq;
    gq.x = gv.x * qv.x; gq.y = gv.y * qv.y; gq.z = gv.z * qv.z; gq.w = gv.w * qv.w;
    ((float4*)(d_gqk + (size_t)b * DD))[t] = gq;
    float c1 = gq.x + gq.y + gq.z + gq.w;
    float c2 = fmaf(bv.x, qv.x, fmaf(bv.y, qv.y, fmaf(bv.z, qv.z, bv.w * qv.w)));
    float4 ln = ((const float4*)(d_LNs + (size_t)b * DD))[t];
    float4 wq = ((const float4*)d_wqbk)[t];
    float bkq = fmaf(ln.x, wq.x, fmaf(ln.y, wq.y, fmaf(ln.z, wq.z, ln.w * wq.w)));
    bred3_128(c1, c2, bkq);
    if (t == 0) {
        d_c1[b] = c1;
        d_c2[b] = c2 + (bkq + d_bqbk) * INV_SCALE;
    }
}

// ---------------- main fused LN + scores + online softmax + weighted accumulation ----------------
__global__ void __launch_bounds__(256) k_attn(const float* __restrict__ price,
                                              float* __restrict__ attn_out) {
    int b = blockIdx.x;
    int t = threadIdx.x, w = t >> 5, l = t & 31;

    __shared__ float s_sc[SS];
    __shared__ float s_wm[8], s_wz[8], s_wt[8];
    __shared__ float s_y[8][DD];  // 16 KB

    const float4* gq4 = (const float4*)(d_gqk + (size_t)b * DD);
    float4 gq[4];
#pragma unroll
    for (int i = 0; i < 4; i++) gq[i] = gq4[l + 32 * i];
    const float c1 = d_c1[b], c2 = d_c2[b];

    float yac[4][4];
#pragma unroll
    for (int i = 0; i < 4; i++)
#pragma unroll
        for (int j = 0; j < 4; j++) yac[i][j] = 0.f;

    float M = -1e30f, Z = 0.f, T = 0.f;

    const float4* base = (const float4*)(price + ((size_t)b * SS + (size_t)w * 64) * DD);

    for (int s = 0; s < 64; s++) {
        const float4* xr = base + (size_t)s * (DD / 4);
        float4 x0 = xr[l], x1 = xr[l + 32], x2 = xr[l + 64], x3 = xr[l + 96];

        float sx = 0.f, sxx = 0.f, sxg = 0.f;
#define ACC4(v, g) do { \
        sx += v.x + v.y + v.z + v.w; \
        sxx = fmaf(v.x, v.x, fmaf(v.y, v.y, fmaf(v.z, v.z, fmaf(v.w, v.w, sxx)))); \
        sxg = fmaf(v.x, g.x, fmaf(v.y, g.y, fmaf(v.z, g.z, fmaf(v.w, g.w, sxg)))); } while (0)
        ACC4(x0, gq[0]); ACC4(x1, gq[1]); ACC4(x2, gq[2]); ACC4(x3, gq[3]);
#undef ACC4

#pragma unroll
        for (int o = 16; o; o >>= 1) {
            sx  += __shfl_xor_sync(0xffffffffu, sx, o);
            sxx += __shfl_xor_sync(0xffffffffu, sxx, o);
            sxg += __shfl_xor_sync(0xffffffffu, sxg, o);
        }
        float m = sx * (1.0f / DD);
        float var = sxx * (1.0f / DD) - m * m;
        float r = rsqrtf(var + LN_EPS);
        float sc = fmaf(r, sxg - m * c1, c2);
        if (l == 0) s_sc[w * 64 + s] = sc;

        float wgt;
        if (sc > M) {                      // warp-uniform (post-butterfly)
            float corr = __expf(M - sc);
            Z *= corr; T *= corr;
#pragma unroll
            for (int i = 0; i < 4; i++)
#pragma unroll
                for (int j = 0; j < 4; j++) yac[i][j] *= corr;
            M = sc;
            wgt = 1.0f;
        } else {
            wgt = __expf(sc - M);
        }
        Z += wgt;
        float cw = wgt * r;
        T = fmaf(cw, m, T);
        yac[0][0] = fmaf(cw, x0.x, yac[0][0]); yac[0][1] = fmaf(cw, x0.y, yac[0][1]);
        yac[0][2] = fmaf(cw, x0.z, yac[0][2]); yac[0][3] = fmaf(cw, x0.w, yac[0][3]);
        yac[1][0] = fmaf(cw, x1.x, yac[1][0]); yac[1][1] = fmaf(cw, x1.y, yac[1][1]);
        yac[1][2] = fmaf(cw, x1.z, yac[1][2]); yac[1][3] = fmaf(cw, x1.w, yac[1][3]);
        yac[2][0] = fmaf(cw, x2.x, yac[2][0]); yac[2][1] = fmaf(cw, x2.y, yac[2][1]);
        yac[2][2] = fmaf(cw, x2.z, yac[2][2]); yac[2][3] = fmaf(cw, x2.w, yac[2][3]);
        yac[3][0] = fmaf(cw, x3.x, yac[3][0]); yac[3][1] = fmaf(cw, x3.y, yac[3][1]);
        yac[3][2] = fmaf(cw, x3.z, yac[3][2]); yac[3][3] = fmaf(cw, x3.w, yac[3][3]);
    }

    if (l == 0) { s_wm[w] = M; s_wz[w] = Z; s_wt[w] = T; }
    __syncthreads();

    float gM = s_wm[0];
#pragma unroll
    for (int i = 1; i < 8; i++) gM = fmaxf(gM, s_wm[i]);
    float Zg = 0.f, Tg = 0.f;
#pragma unroll
    for (int i = 0; i < 8; i++) {
        float e = __expf(s_wm[i] - gM);
        Zg = fmaf(s_wz[i], e, Zg);
        Tg = fmaf(s_wt[i], e, Tg);
    }
    float myf = __expf(M - gM);
#pragma unroll
    for (int i = 0; i < 4; i++) {
        float4 v = make_float4(yac[i][0] * myf, yac[i][1] * myf, yac[i][2] * myf, yac[i][3] * myf);
        *(float4*)&s_y[w][4 * (l + 32 * i)] = v;
    }
    __syncthreads();

    float invZ = 1.0f / Zg;
    for (int e = t; e < DD; e += 256) {
        float acc = 0.f;
#pragma unroll
        for (int w2 = 0; w2 < 8; w2++) acc += s_y[w2][e];
        d_yv[(size_t)b * DD + e] = acc * invZ;
    }
    if (t == 0) d_tv[b] = Tg * invZ;
    for (int s = t; s < SS; s += 256)
        attn_out[(size_t)b * SS + s] = __expf(s_sc[s] - gM) * invZ;
}

// ---------------- bvo[d] = bo[d] + sum_e bv[e]*Wo[e,d] ----------------
__global__ void k_bvo(const float* __restrict__ bv, const float* __restrict__ bo,
                      const float* __restrict__ Wo) {
    int d = blockIdx.x * 128 + threadIdx.x;
    float a = bo[d];
    for (int e = 0; e < DD; e++) a = fmaf(bv[e], Wo[(size_t)e * DD + d], a);
    d_bvo[d] = a;
}

// ---------------- LNattn[b,e] = g_kv[e]*(y - t[b]) + beta_kv[e] ----------------
__global__ void k_lnattn(const float* __restrict__ g_kv, const float* __restrict__ beta_kv) {
    int i = blockIdx.x * 256 + threadIdx.x;
    int b = i >> 9, e = i & 511;
    d_LNa[i] = fmaf(g_kv[e], d_yv[i] - d_tv[b], beta_kv[e]);
}

// ---------------- fused = sigmoid(G)*ctxo + (1-sigmoid(G))*sent ----------------
__global__ void k_fuse(const float* __restrict__ sent, float* __restrict__ out) {
    int i = blockIdx.x * 256 + threadIdx.x;
    float g = d_G[i];
    float a = 1.0f / (1.0f + __expf(-g));
    out[i] = fmaf(a, d_ctxo[i] - sent[i], sent[i]);
}

// ---------------- small-tile SGEMM: 32x32 tile, 64 threads, 4x4 per thread ----------------
// EPI: 0 = store, 1 = store + bias[col], 2 = accumulate into C
template <int TRANSB, int EPI>
__global__ void __launch_bounds__(64) k_sgemm32(const float* __restrict__ A,
                                                const float* __restrict__ Bm,
                                                const float* __restrict__ bias,
                                                float* __restrict__ C,
                                                int M, int N, int K) {
    __shared__ float As[32][36];
    __shared__ float Bs[32][36];
    int t = threadIdx.x;
    int tx = t & 7, ty = t >> 3;
    int m0 = blockIdx.y * 32, n0 = blockIdx.x * 32;
    float acc[4][4];
#pragma unroll
    for (int i = 0; i < 4; i++)
#pragma unroll
        for (int j = 0; j < 4; j++) acc[i][j] = 0.f;

    for (int kt = 0; kt < K; kt += 32) {
#pragma unroll
        for (int i = 0; i < 4; i++) {
            int slot = t + 64 * i;
            int r = slot >> 3, q = slot & 7;
            float4 va = *(const float4*)(A + (size_t)(m0 + r) * K + kt + q * 4);
            As[q * 4 + 0][r] = va.x; As[q * 4 + 1][r] = va.y;
            As[q * 4 + 2][r] = va.z; As[q * 4 + 3][r] = va.w;
            if (TRANSB) {
                float4 vb = *(const float4*)(Bm + (size_t)(n0 + r) * K + kt + q * 4);
                Bs[q * 4 + 0][r] = vb.x; Bs[q * 4 + 1][r] = vb.y;
                Bs[q * 4 + 2][r] = vb.z; Bs[q * 4 + 3][r] = vb.w;
            } else {
                float4 vb = *(const float4*)(Bm + (size_t)(kt + r) * N + n0 + q * 4);
                *(float4*)(&Bs[r][q * 4]) = vb;
            }
        }
        __syncthreads();
#pragma unroll
        for (int k = 0; k < 32; k++) {
            float4 a = *(const float4*)(&As[k][ty * 4]);
            float4 bv = *(const float4*)(&Bs[k][tx * 4]);
            float ar[4] = {a.x, a.y, a.z, a.w};
            float br[4] = {bv.x, bv.y, bv.z, bv.w};
#pragma unroll
            for (int i = 0; i < 4; i++)
#pragma unroll
                for (int j = 0; j < 4; j++) acc[i][j] = fmaf(ar[i], br[j], acc[i][j]);
        }
        __syncthreads();
    }

#pragma unroll
    for (int i = 0; i < 4; i++) {
        int row = m0 + ty * 4 + i;
        float* cp = C + (size_t)row * N + n0 + tx * 4;
        float4 v = make_float4(acc[i][0], acc[i][1], acc[i][2], acc[i][3]);
        if (EPI == 1) {
            const float* bp = bias + n0 + tx * 4;
            v.x += bp[0]; v.y += bp[1]; v.z += bp[2]; v.w += bp[3];
        }
        if (EPI == 2) {
            float4 o = *(const float4*)cp;
            v.x += o.x; v.y += o.y; v.z += o.z; v.w += o.w;
        }
        *(float4*)cp = v;
    }
}

// ---------------- launch ----------------
extern "C" void kernel_launch(void* const* d_in, const int* in_sizes, int n_in,
                              void* d_out, int out_size) {
    const float* sent    = (const float*)d_in[0];
    const float* price   = (const float*)d_in[1];
    const float* Wq      = (const float*)d_in[2];
    const float* bq      = (const float*)d_in[3];
    const float* Wk      = (const float*)d_in[4];
    const float* bk      = (const float*)d_in[5];
    const float* Wv      = (const float*)d_in[6];
    const float* bv      = (const float*)d_in[7];
    const float* Wo      = (const float*)d_in[8];
    const float* bo      = (const float*)d_in[9];
    const float* Wg      = (const float*)d_in[10];
    const float* bg      = (const float*)d_in[11];
    const float* g_q     = (const float*)d_in[12];
    const float* beta_q  = (const float*)d_in[13];
    const float* g_kv    = (const float*)d_in[14];
    const float* beta_kv = (const float*)d_in[15];
    float* out = (float*)d_out;

    float *pWqk, *pLNs, *pqk, *pLNa, *pWvo, *pbvo, *pctxo, *pG;
    cudaGetSymbolAddress((void**)&pWqk,  d_Wqk);
    cudaGetSymbolAddress((void**)&pLNs,  d_LNs);
    cudaGetSymbolAddress((void**)&pqk,   d_qk);
    cudaGetSymbolAddress((void**)&pLNa,  d_LNa);
    cudaGetSymbolAddress((void**)&pWvo,  d_Wvo);
    cudaGetSymbolAddress((void**)&pbvo,  d_bvo);
    cudaGetSymbolAddress((void**)&pctxo, d_ctxo);
    cudaGetSymbolAddress((void**)&pG,    d_G);

    dim3 g16(16, 16);

    k_ln_sent<<<BB, 128>>>(sent, g_q, beta_q);
    k_bias_prep<<<DD, 128>>>(Wk, bq, Wq, bk);
    k_sgemm32<1, 0><<<g16, 64>>>(Wq, Wk, nullptr, pWqk, DD, DD, DD);      // Wqk = Wq @ Wk^T
    k_sgemm32<0, 0><<<g16, 64>>>(pLNs, pWqk, nullptr, pqk, BB, DD, DD);   // qk = LNs @ Wqk
    k_prep<<<BB, 128>>>(g_kv, beta_kv);
    k_attn<<<BB, 256>>>(price, out + (size_t)BB * DD);                    // attn out + y,t
    k_sgemm32<0, 0><<<g16, 64>>>(Wv, Wo, nullptr, pWvo, DD, DD, DD);      // Wvo = Wv @ Wo
    k_bvo<<<4, 128>>>(bv, bo, Wo);
    k_lnattn<<<(BB * DD) / 256, 256>>>(g_kv, beta_kv);
    k_sgemm32<0, 1><<<g16, 64>>>(pLNa, pWvo, pbvo, pctxo, BB, DD, DD);    // ctxo
    k_sgemm32<0, 1><<<g16, 64>>>(sent, Wg, bg, pG, BB, DD, DD);           // gate top half
    k_sgemm32<0, 2><<<g16, 64>>>(pctxo, Wg + (size_t)DD * DD, nullptr, pG, BB, DD, DD); // gate bottom
    k_fuse<<<(BB * DD) / 256, 256>>>(sent, out);
}

// round 3
// speedup vs baseline: 1.2742x; 1.2742x over previous
#include <cuda_runtime.h>

#define BB 512
#define SS 512
#define DD 512
#define LN_EPS 1e-5f
#define INV_SCALE 0.125f   // 1/sqrt(64)

// ---------------- scratch ----------------
__device__ float d_LNs[BB*DD];    // LN(sentiment)
__device__ float d_q[BB*DD];      // LNs @ Wq + bq
__device__ float d_u[BB*DD];      // q @ Wk^T
__device__ float d_gqk[BB*DD];    // g_kv * u / 8
__device__ float d_c1[BB];
__device__ float d_c2[BB];
__device__ float d_LNa[BB*DD];    // attn-weighted LN_kv vector
__device__ float d_Wvo[DD*DD];    // Wv @ Wo
__device__ float d_bvo[DD];       // bv @ Wo + bo
__device__ float d_ctxo[BB*DD];   // context after Wo
__device__ float d_G[BB*DD];      // gate pre-activation (top half)

// ---------------- block reduction (128 threads, 2 values) ----------------
__device__ __forceinline__ void bred2_128(float& a, float& b) {
#pragma unroll
    for (int o = 16; o; o >>= 1) {
        a += __shfl_xor_sync(0xffffffffu, a, o);
        b += __shfl_xor_sync(0xffffffffu, b, o);
    }
    __shared__ float sa[4], sb[4];
    int w = threadIdx.x >> 5;
    if ((threadIdx.x & 31) == 0) { sa[w] = a; sb[w] = b; }
    __syncthreads();
    a = sa[0] + sa[1] + sa[2] + sa[3];
    b = sb[0] + sb[1] + sb[2] + sb[3];
}

// ---------------- LN of sentiment ----------------
__global__ void k_ln_sent(const float* __restrict__ sent,
                          const float* __restrict__ g, const float* __restrict__ be) {
    int b = blockIdx.x, t = threadIdx.x;
    const float4* row = (const float4*)(sent + (size_t)b * DD);
    float4 x = row[t];
    float s = x.x + x.y + x.z + x.w;
    float ss = fmaf(x.x, x.x, fmaf(x.y, x.y, fmaf(x.z, x.z, x.w * x.w)));
    bred2_128(s, ss);
    float m = s * (1.0f / DD);
    float var = ss * (1.0f / DD) - m * m;
    float r = rsqrtf(var + LN_EPS);
    float4 gg = ((const float4*)g)[t];
    float4 bb = ((const float4*)be)[t];
    float4 o;
    o.x = (x.x - m) * r * gg.x + bb.x;
    o.y = (x.y - m) * r * gg.y + bb.y;
    o.z = (x.z - m) * r * gg.z + bb.z;
    o.w = (x.w - m) * r * gg.w + bb.w;
    ((float4*)(d_LNs + (size_t)b * DD))[t] = o;
}

// ---------------- per-batch score constants from q, u ----------------
__global__ void k_prep(const float* __restrict__ bk,
                       const float* __restrict__ g_kv, const float* __restrict__ beta_kv) {
    int b = blockIdx.x, t = threadIdx.x;
    float4 u4 = ((const float4*)(d_u + (size_t)b * DD))[t];
    float4 q4 = ((const float4*)(d_q + (size_t)b * DD))[t];
    float4 g4 = ((const float4*)g_kv)[t];
    float4 be4 = ((const float4*)beta_kv)[t];
    float4 bk4 = ((const float4*)bk)[t];
    float4 gq;
    gq.x = g4.x * u4.x * INV_SCALE;
    gq.y = g4.y * u4.y * INV_SCALE;
    gq.z = g4.z * u4.z * INV_SCALE;
    gq.w = g4.w * u4.w * INV_SCALE;
    ((float4*)(d_gqk + (size_t)b * DD))[t] = gq;
    float c1 = gq.x + gq.y + gq.z + gq.w;
    float c2 = fmaf(be4.x, u4.x, fmaf(be4.y, u4.y, fmaf(be4.z, u4.z, be4.w * u4.w)))
             + fmaf(q4.x, bk4.x, fmaf(q4.y, bk4.y, fmaf(q4.z, bk4.z, q4.w * bk4.w)));
    bred2_128(c1, c2);
    if (t == 0) {
        d_c1[b] = c1;
        d_c2[b] = c2 * INV_SCALE;   // (beta.u + q.bk)/8  (beta term already /8? no:)
    }
}
// NOTE on c2: gq already carries 1/8, so beta.u must also be scaled by 1/8 and q.bk by 1/8.
// Above we accumulate beta.u (unscaled) + q.bk (unscaled), then multiply by INV_SCALE. Correct.

// ---------------- fused LN + scores + online softmax + weighted accum (+LNa epilogue) ----------------
__global__ void __launch_bounds__(256) k_attn(const float* __restrict__ price,
                                              const float* __restrict__ g_kv,
                                              const float* __restrict__ beta_kv,
                                              float* __restrict__ attn_out) {
    int b = blockIdx.x;
    int t = threadIdx.x, w = t >> 5, l = t & 31;

    __shared__ float s_sc[SS];
    __shared__ float s_wm[8], s_wz[8], s_wt[8];
    __shared__ float s_y[8][DD];

    const float4* gq4 = (const float4*)(d_gqk + (size_t)b * DD);
    float4 gq[4];
#pragma unroll
    for (int i = 0; i < 4; i++) gq[i] = gq4[l + 32 * i];
    const float c1 = d_c1[b], c2 = d_c2[b];

    float yac[4][4];
#pragma unroll
    for (int i = 0; i < 4; i++)
#pragma unroll
        for (int j = 0; j < 4; j++) yac[i][j] = 0.f;

    float M = -1e30f, Z = 0.f, T = 0.f;

    const float4* base = (const float4*)(price + ((size_t)b * SS + (size_t)w * 64) * DD);

    for (int s = 0; s < 64; s++) {
        const float4* xr = base + (size_t)s * (DD / 4);
        float4 x0 = xr[l], x1 = xr[l + 32], x2 = xr[l + 64], x3 = xr[l + 96];

        float sx = 0.f, sxx = 0.f, sxg = 0.f;
#define ACC4(v, g) do { \
        sx += v.x + v.y + v.z + v.w; \
        sxx = fmaf(v.x, v.x, fmaf(v.y, v.y, fmaf(v.z, v.z, fmaf(v.w, v.w, sxx)))); \
        sxg = fmaf(v.x, g.x, fmaf(v.y, g.y, fmaf(v.z, g.z, fmaf(v.w, g.w, sxg)))); } while (0)
        ACC4(x0, gq[0]); ACC4(x1, gq[1]); ACC4(x2, gq[2]); ACC4(x3, gq[3]);
#undef ACC4

#pragma unroll
        for (int o = 16; o; o >>= 1) {
            sx  += __shfl_xor_sync(0xffffffffu, sx, o);
            sxx += __shfl_xor_sync(0xffffffffu, sxx, o);
            sxg += __shfl_xor_sync(0xffffffffu, sxg, o);
        }
        float m = sx * (1.0f / DD);
        float var = sxx * (1.0f / DD) - m * m;
        float r = rsqrtf(var + LN_EPS);
        float sc = fmaf(r, sxg - m * c1, c2);
        if (l == 0) s_sc[w * 64 + s] = sc;

        float wgt;
        if (sc > M) {   // warp-uniform after butterfly reduction
            float corr = __expf(M - sc);
            Z *= corr; T *= corr;
#pragma unroll
            for (int i = 0; i < 4; i++)
#pragma unroll
                for (int j = 0; j < 4; j++) yac[i][j] *= corr;
            M = sc;
            wgt = 1.0f;
        } else {
            wgt = __expf(sc - M);
        }
        Z += wgt;
        float cw = wgt * r;
        T = fmaf(cw, m, T);
        yac[0][0] = fmaf(cw, x0.x, yac[0][0]); yac[0][1] = fmaf(cw, x0.y, yac[0][1]);
        yac[0][2] = fmaf(cw, x0.z, yac[0][2]); yac[0][3] = fmaf(cw, x0.w, yac[0][3]);
        yac[1][0] = fmaf(cw, x1.x, yac[1][0]); yac[1][1] = fmaf(cw, x1.y, yac[1][1]);
        yac[1][2] = fmaf(cw, x1.z, yac[1][2]); yac[1][3] = fmaf(cw, x1.w, yac[1][3]);
        yac[2][0] = fmaf(cw, x2.x, yac[2][0]); yac[2][1] = fmaf(cw, x2.y, yac[2][1]);
        yac[2][2] = fmaf(cw, x2.z, yac[2][2]); yac[2][3] = fmaf(cw, x2.w, yac[2][3]);
        yac[3][0] = fmaf(cw, x3.x, yac[3][0]); yac[3][1] = fmaf(cw, x3.y, yac[3][1]);
        yac[3][2] = fmaf(cw, x3.z, yac[3][2]); yac[3][3] = fmaf(cw, x3.w, yac[3][3]);
    }

    if (l == 0) { s_wm[w] = M; s_wz[w] = Z; s_wt[w] = T; }
    __syncthreads();

    float gM = s_wm[0];
#pragma unroll
    for (int i = 1; i < 8; i++) gM = fmaxf(gM, s_wm[i]);
    float Zg = 0.f, Tg = 0.f;
#pragma unroll
    for (int i = 0; i < 8; i++) {
        float e = __expf(s_wm[i] - gM);
        Zg = fmaf(s_wz[i], e, Zg);
        Tg = fmaf(s_wt[i], e, Tg);
    }
    float myf = __expf(M - gM);
#pragma unroll
    for (int i = 0; i < 4; i++) {
        float4 v = make_float4(yac[i][0] * myf, yac[i][1] * myf, yac[i][2] * myf, yac[i][3] * myf);
        *(float4*)&s_y[w][4 * (l + 32 * i)] = v;
    }
    __syncthreads();

    float invZ = 1.0f / Zg;
    float tvv = Tg * invZ;
    for (int e = t; e < DD; e += 256) {
        float acc = 0.f;
#pragma unroll
        for (int w2 = 0; w2 < 8; w2++) acc += s_y[w2][e];
        // LNa = g_kv*(yv - tv) + beta_kv, directly (fused former k_lnattn)
        d_LNa[(size_t)b * DD + e] = fmaf(g_kv[e], acc * invZ - tvv, beta_kv[e]);
    }
    for (int s = t; s < SS; s += 256)
        attn_out[(size_t)b * SS + s] = __expf(s_sc[s] - gM) * invZ;
}

// ---------------- bvo[d] = bo[d] + sum_e bv[e]*Wo[e,d] ----------------
__global__ void k_bvo(const float* __restrict__ bv, const float* __restrict__ bo,
                      const float* __restrict__ Wo) {
    int d = blockIdx.x * 128 + threadIdx.x;
    float a0 = 0.f, a1 = 0.f, a2 = 0.f, a3 = 0.f;
    for (int e = 0; e < DD; e += 4) {
        a0 = fmaf(bv[e + 0], Wo[(size_t)(e + 0) * DD + d], a0);
        a1 = fmaf(bv[e + 1], Wo[(size_t)(e + 1) * DD + d], a1);
        a2 = fmaf(bv[e + 2], Wo[(size_t)(e + 2) * DD + d], a2);
        a3 = fmaf(bv[e + 3], Wo[(size_t)(e + 3) * DD + d], a3);
    }
    d_bvo[d] = a0 + a1 + a2 + a3 + bo[d];
}

// ---------------- SGEMM: 32x64 tile, 128 threads, 4x4/thread, K-tile 32, double-buffered ----------------
// All matrices 512x512, stride 512. TRANSB: B stored [N,K]. 
// EPI: 0 = store, 1 = store + bias[col], 2 = gate-fuse (Gtop in `bias`, X1=ctxo, X2=sent, C=out)
template <int TRANSB, int EPI>
__global__ void __launch_bounds__(128) k_gemm(const float* __restrict__ A,
                                              const float* __restrict__ Bm,
                                              const float* __restrict__ bias,
                                              float* __restrict__ C,
                                              const float* __restrict__ X1,
                                              const float* __restrict__ X2) {
    __shared__ float As[2][32][36];
    __shared__ float Bs[2][32][68];
    const int t = threadIdx.x;
    const int tx = t & 15, ty = t >> 4;
    const int m0 = blockIdx.y * 32, n0 = blockIdx.x * 64;

    // A load map: idx = t + 128*i (i<2) -> row (t>>3)+16i, quad t&7
    const int arA = t >> 3, aq = t & 7;
    const float* Abase = A + (size_t)(m0 + arA) * DD + aq * 4;
    // B load maps
    const int brB = t >> 4, bq = t & 15;     // !TRANSB: row (brB+8i), quad bq
    const int nrB = t >> 3;                  // TRANSB: n-row (nrB+16i), quad aq
    const float* Bbase = TRANSB ? (Bm + (size_t)(n0 + nrB) * DD + aq * 4)
                                : (Bm + (size_t)brB * DD + n0 + bq * 4);

    float acc[4][4];
#pragma unroll
    for (int i = 0; i < 4; i++)
#pragma unroll
        for (int j = 0; j < 4; j++) acc[i][j] = 0.f;

    float4 aP[2], bP[4];

    // --- prefetch tile 0 ---
    aP[0] = *(const float4*)(Abase);
    aP[1] = *(const float4*)(Abase + 16 * DD);
#pragma unroll
    for (int i = 0; i < 4; i++)
        bP[i] = TRANSB ? *(const float4*)(Bbase + (size_t)(16 * i) * DD)
                       : *(const float4*)(Bbase + (size_t)(8 * i) * DD);

    // store tile 0 into buffer 0
    {
        As[0][aq * 4 + 0][arA] = aP[0].x; As[0][aq * 4 + 1][arA] = aP[0].y;
        As[0][aq * 4 + 2][arA] = aP[0].z; As[0][aq * 4 + 3][arA] = aP[0].w;
        As[0][aq * 4 + 0][arA + 16] = aP[1].x; As[0][aq * 4 + 1][arA + 16] = aP[1].y;
        As[0][aq * 4 + 2][arA + 16] = aP[1].z; As[0][aq * 4 + 3][arA + 16] = aP[1].w;
        if (TRANSB) {
#pragma unroll
            for (int i = 0; i < 4; i++) {
                Bs[0][aq * 4 + 0][nrB + 16 * i] = bP[i].x;
                Bs[0][aq * 4 + 1][nrB + 16 * i] = bP[i].y;
                Bs[0][aq * 4 + 2][nrB + 16 * i] = bP[i].z;
                Bs[0][aq * 4 + 3][nrB + 16 * i] = bP[i].w;
            }
        } else {
#pragma unroll
            for (int i = 0; i < 4; i++)
                *(float4*)&Bs[0][brB + 8 * i][bq * 4] = bP[i];
        }
    }
    __syncthreads();

    int buf = 0;
#pragma unroll 1
    for (int kt = 0; kt < 16; kt++) {
        if (kt < 15) {
            int ko = (kt + 1) * 32;
            aP[0] = *(const float4*)(Abase + ko);
            aP[1] = *(const float4*)(Abase + 16 * DD + ko);
#pragma unroll
            for (int i = 0; i < 4; i++)
                bP[i] = TRANSB ? *(const float4*)(Bbase + (size_t)(16 * i) * DD + ko)
                               : *(const float4*)(Bbase + (size_t)(ko + 8 * i) * DD);
        }
#pragma unroll
        for (int k = 0; k < 32; k++) {
            float4 a4 = *(const float4*)&As[buf][k][ty * 4];
            float4 b4 = *(const float4*)&Bs[buf][k][tx * 4];
            float ar[4] = {a4.x, a4.y, a4.z, a4.w};
            float br[4] = {b4.x, b4.y, b4.z, b4.w};
#pragma unroll
            for (int i = 0; i < 4; i++)
#pragma unroll
                for (int j = 0; j < 4; j++) acc[i][j] = fmaf(ar[i], br[j], acc[i][j]);
        }
        if (kt < 15) {
            int nb = buf ^ 1;
            As[nb][aq * 4 + 0][arA] = aP[0].x; As[nb][aq * 4 + 1][arA] = aP[0].y;
            As[nb][aq * 4 + 2][arA] = aP[0].z; As[nb][aq * 4 + 3][arA] = aP[0].w;
            As[nb][aq * 4 + 0][arA + 16] = aP[1].x; As[nb][aq * 4 + 1][arA + 16] = aP[1].y;
            As[nb][aq * 4 + 2][arA + 16] = aP[1].z; As[nb][aq * 4 + 3][arA + 16] = aP[1].w;
            if (TRANSB) {
#pragma unroll
                for (int i = 0; i < 4; i++) {
                    Bs[nb][aq * 4 + 0][nrB + 16 * i] = bP[i].x;
                    Bs[nb][aq * 4 + 1][nrB + 16 * i] = bP[i].y;
                    Bs[nb][aq * 4 + 2][nrB + 16 * i] = bP[i].z;
                    Bs[nb][aq * 4 + 3][nrB + 16 * i] = bP[i].w;
                }
            } else {
#pragma unroll
                for (int i = 0; i < 4; i++)
                    *(float4*)&Bs[nb][brB + 8 * i][bq * 4] = bP[i];
            }
        }
        __syncthreads();
        buf ^= 1;
    }

#pragma unroll
    for (int i = 0; i < 4; i++) {
        int row = m0 + ty * 4 + i;
        float* cp = C + (size_t)row * DD + n0 + tx * 4;
        float4 v = make_float4(acc[i][0], acc[i][1], acc[i][2], acc[i][3]);
        if (EPI == 1) {
            const float* bp = bias + n0 + tx * 4;
            v.x += bp[0]; v.y += bp[1]; v.z += bp[2]; v.w += bp[3];
        }
        if (EPI == 2) {
            const float4 gt = *(const float4*)(bias + (size_t)row * DD + n0 + tx * 4);
            const float4 cx = *(const float4*)(X1 + (size_t)row * DD + n0 + tx * 4);
            const float4 sn = *(const float4*)(X2 + (size_t)row * DD + n0 + tx * 4);
            float ax = 1.0f / (1.0f + __expf(-(gt.x + v.x)));
            float ay = 1.0f / (1.0f + __expf(-(gt.y + v.y)));
            float az = 1.0f / (1.0f + __expf(-(gt.z + v.z)));
            float aw = 1.0f / (1.0f + __expf(-(gt.w + v.w)));
            v.x = fmaf(ax, cx.x - sn.x, sn.x);
            v.y = fmaf(ay, cx.y - sn.y, sn.y);
            v.z = fmaf(az, cx.z - sn.z, sn.z);
            v.w = fmaf(aw, cx.w - sn.w, sn.w);
        }
        *(float4*)cp = v;
    }
}

// ---------------- launch ----------------
extern "C" void kernel_launch(void* const* d_in, const int* in_sizes, int n_in,
                              void* d_out, int out_size) {
    const float* sent    = (const float*)d_in[0];
    const float* price   = (const float*)d_in[1];
    const float* Wq      = (const float*)d_in[2];
    const float* bq      = (const float*)d_in[3];
    const float* Wk      = (const float*)d_in[4];
    const float* bk      = (const float*)d_in[5];
    const float* Wv      = (const float*)d_in[6];
    const float* bv      = (const float*)d_in[7];
    const float* Wo      = (const float*)d_in[8];
    const float* bo      = (const float*)d_in[9];
    const float* Wg      = (const float*)d_in[10];
    const float* bg      = (const float*)d_in[11];
    const float* g_q     = (const float*)d_in[12];
    const float* beta_q  = (const float*)d_in[13];
    const float* g_kv    = (const float*)d_in[14];
    const float* beta_kv = (const float*)d_in[15];
    float* out = (float*)d_out;

    float *pLNs, *pq, *pu, *pLNa, *pWvo, *pbvo, *pctxo, *pG;
    cudaGetSymbolAddress((void**)&pLNs,  d_LNs);
    cudaGetSymbolAddress((void**)&pq,    d_q);
    cudaGetSymbolAddress((void**)&pu,    d_u);
    cudaGetSymbolAddress((void**)&pLNa,  d_LNa);
    cudaGetSymbolAddress((void**)&pWvo,  d_Wvo);
    cudaGetSymbolAddress((void**)&pbvo,  d_bvo);
    cudaGetSymbolAddress((void**)&pctxo, d_ctxo);
    cudaGetSymbolAddress((void**)&pG,    d_G);

    dim3 gg(DD / 64, 512 / 32);   // 8 x 16 = 128 blocks

    // independent weight-side work first
    k_gemm<0, 0><<<gg, 128>>>(Wv, Wo, nullptr, pWvo, nullptr, nullptr);       // Wvo = Wv @ Wo
    k_bvo<<<4, 128>>>(bv, bo, Wo);                                            // bvo
    k_gemm<0, 1><<<gg, 128>>>(sent, Wg, bg, pG, nullptr, nullptr);            // Gtop = sent@Wg_top + bg

    // query chain
    k_ln_sent<<<BB, 128>>>(sent, g_q, beta_q);                                // LNs
    k_gemm<0, 1><<<gg, 128>>>(pLNs, Wq, bq, pq, nullptr, nullptr);            // q = LNs@Wq + bq
    k_gemm<1, 0><<<gg, 128>>>(pq, Wk, nullptr, pu, nullptr, nullptr);         // u = q @ Wk^T
    k_prep<<<BB, 128>>>(bk, g_kv, beta_kv);                                   // gqk, c1, c2

    // main fused attention pass (writes attn output + LNa)
    k_attn<<<BB, 256>>>(price, g_kv, beta_kv, out + (size_t)BB * DD);

    // output chain
    k_gemm<0, 1><<<gg, 128>>>(pLNa, pWvo, pbvo, pctxo, nullptr, nullptr);     // ctxo
    k_gemm<0, 2><<<gg, 128>>>(pctxo, Wg + (size_t)DD * DD, pG, out, pctxo, sent); // G bottom + sigmoid + fuse
}